// round 1
// baseline (speedup 1.0000x reference)
#include <cuda_runtime.h>
#include <cstdint>
#include <cstddef>

// Problem constants (fixed shapes from the reference)
#define N_SRC0   286000
#define N_DST0   11000
#define N_E0     275000
#define N_DST1   1000
#define N_E1     10000
#define F_IN     602
#define HID      256
#define NCLS     41

// ---------------- scratch (device globals; no runtime allocation) ----------
__device__ int   g_cnt0[N_DST0];
__device__ int   g_cur0[N_DST0];
__device__ int   g_off0[N_DST0 + 1];
__device__ int   g_src0[N_E0];

__device__ int   g_cnt1[N_DST1];
__device__ int   g_cur1[N_DST1];
__device__ int   g_off1[N_DST1 + 1];
__device__ int   g_src1[N_E1];

__device__ float g_hagg0[(size_t)N_DST0 * F_IN];   // ~26.5 MB
__device__ float g_h    [(size_t)N_DST0 * HID];    // ~11.3 MB
__device__ float g_hagg1[(size_t)N_DST1 * HID];    // ~1 MB

// ---------------- setup kernels --------------------------------------------
__global__ void k_zero() {
    int i = blockIdx.x * blockDim.x + threadIdx.x;
    if (i < N_DST0) { g_cnt0[i] = 0; g_cur0[i] = 0; }
    if (i < N_DST1) { g_cnt1[i] = 0; g_cur1[i] = 0; }
}

__global__ void k_count(const int* __restrict__ e0_dst,
                        const int* __restrict__ e1_dst) {
    int i = blockIdx.x * blockDim.x + threadIdx.x;
    if (i < N_E0) atomicAdd(&g_cnt0[e0_dst[i]], 1);
    if (i < N_E1) atomicAdd(&g_cnt1[e1_dst[i]], 1);
}

// single-block exclusive scan (n <= a few tens of thousands)
__device__ void scan_excl(const int* cnt, int* off, int n) {
    __shared__ int sh[1024];
    __shared__ int carry;
    const int t = threadIdx.x;
    if (t == 0) carry = 0;
    __syncthreads();
    for (int base = 0; base < n; base += 1024) {
        int i = base + t;
        int v = (i < n) ? cnt[i] : 0;
        sh[t] = v;
        __syncthreads();
        #pragma unroll
        for (int s = 1; s < 1024; s <<= 1) {
            int tmp = (t >= s) ? sh[t - s] : 0;
            __syncthreads();
            sh[t] += tmp;
            __syncthreads();
        }
        if (i < n) off[i] = carry + sh[t] - v;   // exclusive
        __syncthreads();
        if (t == 0) carry += sh[1023];
        __syncthreads();
    }
    if (t == 0) off[n] = carry;
}

__global__ void k_scan() {
    if (blockIdx.x == 0) scan_excl(g_cnt0, g_off0, N_DST0);
    else                 scan_excl(g_cnt1, g_off1, N_DST1);
}

__global__ void k_scatter(const int* __restrict__ e0_src,
                          const int* __restrict__ e0_dst,
                          const int* __restrict__ e1_src,
                          const int* __restrict__ e1_dst) {
    int i = blockIdx.x * blockDim.x + threadIdx.x;
    if (i < N_E0) {
        int d = e0_dst[i];
        int p = atomicAdd(&g_cur0[d], 1);
        g_src0[g_off0[d] + p] = e0_src[i];
    }
    if (i < N_E1) {
        int d = e1_dst[i];
        int p = atomicAdd(&g_cur1[d], 1);
        g_src1[g_off1[d] + p] = e1_src[i];
    }
}

// ---------------- layer-0 mean aggregation (the big gather) ----------------
// One block per dst node, 128 threads, 5 feature lanes per thread (640 >= 602).
__global__ void k_agg0(const float* __restrict__ x) {
    const int dst = blockIdx.x;
    const int beg = g_off0[dst];
    const int end = g_off0[dst + 1];
    const int t   = threadIdx.x;

    float acc[5] = {0.f, 0.f, 0.f, 0.f, 0.f};
    for (int e = beg; e < end; ++e) {
        const float* row = x + (size_t)g_src0[e] * F_IN;
        #pragma unroll
        for (int j = 0; j < 5; ++j) {
            int f = t + j * 128;
            if (f < F_IN) acc[j] += __ldg(row + f);
        }
    }
    const float inv = (end > beg) ? 1.0f / (float)(end - beg) : 0.0f;
    float* orow = g_hagg0 + (size_t)dst * F_IN;
    #pragma unroll
    for (int j = 0; j < 5; ++j) {
        int f = t + j * 128;
        if (f < F_IN) orow[f] = acc[j] * inv;
    }
}

// ---------------- layer-0 GEMM: h = relu(Xd@Ws + Hagg@Wn + b0) -------------
// 64x64 tile, BK=16, 256 threads, 4x4 micro-tile per thread.
#define BM 64
#define BN 64
#define BKK 16

__global__ void k_gemm0(const float* __restrict__ x,
                        const float* __restrict__ Ws,
                        const float* __restrict__ Wn,
                        const float* __restrict__ bias) {
    __shared__ float As[BKK][BM];
    __shared__ float Bs[BKK][BN];

    const int tid = threadIdx.x;
    const int tx = tid & 15;
    const int ty = tid >> 4;
    const int rowBase = blockIdx.y * BM;
    const int colBase = blockIdx.x * BN;

    float acc[4][4] = {};

    const int ar  = tid >> 2;          // 0..63 : A tile row
    const int akb = (tid & 3) * 4;     // 0,4,8,12 : A tile k base
    const int wk  = tid >> 4;          // 0..15 : W tile k
    const int wn4 = (tid & 15) * 4;    // W tile n base (local)
    const int grow = rowBase + ar;

    for (int phase = 0; phase < 2; ++phase) {
        const float* A = phase ? g_hagg0 : x;
        const float* W = phase ? Wn : Ws;
        const float* arow = (grow < N_DST0) ? (A + (size_t)grow * F_IN) : nullptr;

        for (int k0 = 0; k0 < F_IN; k0 += BKK) {
            #pragma unroll
            for (int u = 0; u < 4; ++u) {
                int k = k0 + akb + u;
                As[akb + u][ar] = (arow && k < F_IN) ? arow[k] : 0.0f;
            }
            {
                int k = k0 + wk;
                float4 w4 = make_float4(0.f, 0.f, 0.f, 0.f);
                if (k < F_IN)
                    w4 = *reinterpret_cast<const float4*>(W + (size_t)k * HID + colBase + wn4);
                *reinterpret_cast<float4*>(&Bs[wk][wn4]) = w4;
            }
            __syncthreads();
            #pragma unroll
            for (int kk = 0; kk < BKK; ++kk) {
                float4 a4 = *reinterpret_cast<const float4*>(&As[kk][ty * 4]);
                float4 b4 = *reinterpret_cast<const float4*>(&Bs[kk][tx * 4]);
                float a[4] = {a4.x, a4.y, a4.z, a4.w};
                float b[4] = {b4.x, b4.y, b4.z, b4.w};
                #pragma unroll
                for (int i = 0; i < 4; ++i)
                    #pragma unroll
                    for (int j = 0; j < 4; ++j)
                        acc[i][j] += a[i] * b[j];
            }
            __syncthreads();
        }
    }

    #pragma unroll
    for (int i = 0; i < 4; ++i) {
        int r = rowBase + ty * 4 + i;
        if (r >= N_DST0) continue;
        #pragma unroll
        for (int j = 0; j < 4; ++j) {
            int c = colBase + tx * 4 + j;
            float v = acc[i][j] + bias[c];
            g_h[(size_t)r * HID + c] = fmaxf(v, 0.0f);
        }
    }
}

// ---------------- layer-1 mean aggregation ---------------------------------
__global__ void k_agg1() {
    const int dst = blockIdx.x;
    const int beg = g_off1[dst];
    const int end = g_off1[dst + 1];
    const int t   = threadIdx.x;     // 256 threads, one feature each

    float acc = 0.f;
    for (int e = beg; e < end; ++e)
        acc += g_h[(size_t)g_src1[e] * HID + t];

    const float inv = (end > beg) ? 1.0f / (float)(end - beg) : 0.0f;
    g_hagg1[(size_t)dst * HID + t] = acc * inv;
}

// ---------------- output layer ----------------------------------------------
__global__ void k_out(const float* __restrict__ Ws1,
                      const float* __restrict__ Wn1,
                      const float* __restrict__ b1,
                      float* __restrict__ out) {
    __shared__ float hd[HID];
    __shared__ float ha[HID];
    const int dst = blockIdx.x;
    for (int i = threadIdx.x; i < HID; i += blockDim.x) {
        hd[i] = g_h[(size_t)dst * HID + i];      // h_dst1 = h[:1000]
        ha[i] = g_hagg1[(size_t)dst * HID + i];
    }
    __syncthreads();
    const int c = threadIdx.x;
    if (c < NCLS) {
        float s = b1[c];
        #pragma unroll 4
        for (int k = 0; k < HID; ++k)
            s += hd[k] * Ws1[k * NCLS + c] + ha[k] * Wn1[k * NCLS + c];
        out[dst * NCLS + c] = s;
    }
}

// ---------------- launch ------------------------------------------------------
extern "C" void kernel_launch(void* const* d_in, const int* in_sizes, int n_in,
                              void* d_out, int out_size) {
    const float* x      = (const float*)d_in[0];
    const float* Wself0 = (const float*)d_in[1];
    const float* Wneigh0= (const float*)d_in[2];
    const float* b0     = (const float*)d_in[3];
    const float* Wself1 = (const float*)d_in[4];
    const float* Wneigh1= (const float*)d_in[5];
    const float* b1     = (const float*)d_in[6];
    const int*   e0_src = (const int*)d_in[7];
    const int*   e0_dst = (const int*)d_in[8];
    const int*   e1_src = (const int*)d_in[9];
    const int*   e1_dst = (const int*)d_in[10];
    float* out = (float*)d_out;

    k_zero   <<<(N_DST0 + 255) / 256, 256>>>();
    k_count  <<<(N_E0   + 255) / 256, 256>>>(e0_dst, e1_dst);
    k_scan   <<<2, 1024>>>();
    k_scatter<<<(N_E0   + 255) / 256, 256>>>(e0_src, e0_dst, e1_src, e1_dst);
    k_agg0   <<<N_DST0, 128>>>(x);
    k_gemm0  <<<dim3(HID / BN, (N_DST0 + BM - 1) / BM), 256>>>(x, Wself0, Wneigh0, b0);
    k_agg1   <<<N_DST1, 256>>>();
    k_out    <<<N_DST1, 64>>>(Wself1, Wneigh1, b1, out);
}